// round 8
// baseline (speedup 1.0000x reference)
#include <cuda_runtime.h>
#include <cuda_fp16.h>
#include <cuda_bf16.h>
#include <math.h>
#include <stdint.h>

// Problem dims
#define BATCH 2048
#define TT    128
#define VV    256
#define CC    32
#define HH    128
#define EE    256
#define GG    384   // 3*H
#define OO    256
#define NLN   3
#define BNK   32

// GRU tiling
#define BM    32      // batch rows per CTA (2 streams x 16)
#define NTH   512     // 16 warps, 24 gate-cols each
// SMEM byte offsets
#define SW0   0                   // w fp16: [384][128] half, swizzled (96KB)
#define SH16(s) (98304 + (s) * 4096)   // h fp16 per stream [16][128]
#define SMEM_TOTAL 106496

// Scratch (static device globals)
__device__ __align__(16) __half g_w0[2 * GG * HH];  // [dir][p][k] fp16 (r,z x0.5)
__device__ float g_xtab[2 * VV * GG];   // permuted x@w_ih^T + biases (r,z x0.5)
__device__ float g_feat[BATCH * EE];
__device__ float g_upwT[NLN * BNK * EE]; // up_w transposed: [l][d][e]
__device__ int   g_tokT[TT * BATCH];     // tokens transposed [t][b]

// ---------------------------------------------------------------------------
// n-gate tanh: (e-1)*rcp(e+1), e = 2^(2x*log2e).  ~1e-7 rel err, 2 MUFU.
// ---------------------------------------------------------------------------
__device__ __forceinline__ float tanh_e(float v) {
    float t = fminf(v * 2.8853900817779268f, 126.0f);
    float e; asm("ex2.approx.f32 %0, %1;" : "=f"(e) : "f"(t));
    float rp; asm("rcp.approx.f32 %0, %1;" : "=f"(rp) : "f"(e + 1.0f));
    return (e - 1.0f) * rp;
}

// ---------------------------------------------------------------------------
// MMA / ldmatrix wrappers
// ---------------------------------------------------------------------------
__device__ __forceinline__ void ldsm4(uint32_t& r0, uint32_t& r1, uint32_t& r2,
                                      uint32_t& r3, uint32_t addr) {
    asm volatile("ldmatrix.sync.aligned.m8n8.x4.shared.b16 {%0,%1,%2,%3}, [%4];"
                 : "=r"(r0), "=r"(r1), "=r"(r2), "=r"(r3) : "r"(addr));
}
__device__ __forceinline__ void mma16816(float* d, const uint32_t* a,
                                         uint32_t b0, uint32_t b1) {
    asm volatile(
        "mma.sync.aligned.m16n8k16.row.col.f32.f16.f16.f32 "
        "{%0,%1,%2,%3}, {%4,%5,%6,%7}, {%8,%9}, {%0,%1,%2,%3};"
        : "+f"(d[0]), "+f"(d[1]), "+f"(d[2]), "+f"(d[3])
        : "r"(a[0]), "r"(a[1]), "r"(a[2]), "r"(a[3]), "r"(b0), "r"(b1));
}

// gate-dim permutation: orig g = t*128 + j -> p = 24*(j>>3) + 8*t + (j&7)
__device__ __forceinline__ int permute_g(int g) {
    int t = g >> 7, j = g & 127;
    return 24 * (j >> 3) + 8 * t + (j & 7);
}

// ---------------------------------------------------------------------------
// Prep A: xtab (permuted). b_ih + b_hh(r,z) folded; r,z entries x0.5
// (sigmoid(x) = 0.5*tanh(x/2)+0.5 with the /2 pre-applied).
// ---------------------------------------------------------------------------
__global__ void xtab_kernel(const float* __restrict__ ce,
                            const float* __restrict__ wih_f, const float* __restrict__ bih_f,
                            const float* __restrict__ wih_b, const float* __restrict__ bih_b,
                            const float* __restrict__ bhh_f, const float* __restrict__ bhh_b) {
    extern __shared__ float xsm[];
    float* ws = xsm;               // [384*32]
    float* bs = ws + GG * CC;      // [384]
    float* cs = bs + GG;           // [32*32]
    const int d = blockIdx.y, g = threadIdx.x;
    const float* wih = d ? wih_b : wih_f;
    const float* bih = d ? bih_b : bih_f;
    const float* bhh = d ? bhh_b : bhh_f;
    for (int i = g; i < GG * CC; i += GG) ws[i] = wih[i];
    bs[g] = bih[g] + (g < 2 * HH ? bhh[g] : 0.0f);
    const int v0 = blockIdx.x * 32;
    for (int i = g; i < 32 * CC; i += GG) cs[i] = ce[v0 * CC + i];
    __syncthreads();
    const int p = permute_g(g);
    const float sc = (g < 2 * HH) ? 0.5f : 1.0f;
    for (int vi = 0; vi < 32; vi++) {
        float s = bs[g];
        #pragma unroll
        for (int c = 0; c < CC; c++) s = fmaf(cs[vi * CC + c], ws[g * CC + c], s);
        g_xtab[(d * VV + v0 + vi) * GG + p] = s * sc;
    }
}

// ---------------------------------------------------------------------------
// Prep B (fused): w_hh fp16 permuted (r,z x0.5) + up_w transpose + tokens
// transpose. grid 1504 x 256.
// ---------------------------------------------------------------------------
__global__ void prep_misc(const float* __restrict__ whh_f,
                          const float* __restrict__ whh_b,
                          const float* __restrict__ up_w,
                          const int* __restrict__ tokens) {
    const int i = blockIdx.x * 256 + threadIdx.x;
    if (i < 2 * GG * HH) {
        int d = i / (GG * HH), rem = i % (GG * HH);
        int g = rem / HH, k = rem % HH;
        const float* w = d ? whh_b : whh_f;
        float v = w[g * HH + k];
        if (g < 2 * HH) v *= 0.5f;
        g_w0[d * GG * HH + permute_g(g) * HH + k] = __float2half_rn(v);
    } else if (i < 2 * GG * HH + NLN * EE * BNK) {
        int j = i - 2 * GG * HH;
        int l = j / (EE * BNK), rem = j % (EE * BNK);
        int e = rem / BNK, dd = rem % BNK;
        g_upwT[(l * BNK + dd) * EE + e] = up_w[j];
    } else {
        int j = i - (2 * GG * HH + NLN * EE * BNK);
        if (j < BATCH * TT) {
            int b = j / TT, t = j % TT;
            g_tokT[t * BATCH + b] = tokens[j];
        }
    }
}

// ---------------------------------------------------------------------------
// GRU via mma. fp16 operands, fp32 accum + fp32 register hprev.
// r,z via packed tanh.f16x2; n via ex2+rcp. xp(s0) prefetched one step ahead.
// grid (64, 2) x 512 threads.
// ---------------------------------------------------------------------------
#define GATE_PAIR(RI, XP, SG) do {                                            \
    float xr0 = XP[RI][0].x + acc[SG][0][2 * (RI) + 0];                       \
    float xr1 = XP[RI][0].y + acc[SG][0][2 * (RI) + 1];                       \
    float xz0 = XP[RI][1].x + acc[SG][1][2 * (RI) + 0];                       \
    float xz1 = XP[RI][1].y + acc[SG][1][2 * (RI) + 1];                       \
    uint32_t xr2, xz2, tr2, tz2;                                              \
    asm("cvt.rn.f16x2.f32 %0, %1, %2;" : "=r"(xr2) : "f"(xr1), "f"(xr0));     \
    asm("cvt.rn.f16x2.f32 %0, %1, %2;" : "=r"(xz2) : "f"(xz1), "f"(xz0));     \
    asm("tanh.approx.f16x2 %0, %1;" : "=r"(tr2) : "r"(xr2));                  \
    asm("tanh.approx.f16x2 %0, %1;" : "=r"(tz2) : "r"(xz2));                  \
    __half2 trh = *reinterpret_cast<__half2*>(&tr2);                          \
    __half2 tzh = *reinterpret_cast<__half2*>(&tz2);                          \
    float r0 = fmaf(__low2float(trh),  0.5f, 0.5f);                           \
    float r1 = fmaf(__high2float(trh), 0.5f, 0.5f);                           \
    float z0 = fmaf(__low2float(tzh),  0.5f, 0.5f);                           \
    float z1 = fmaf(__high2float(tzh), 0.5f, 0.5f);                           \
    float n0 = tanh_e(fmaf(r0, acc[SG][2][2 * (RI) + 0], XP[RI][2].x));       \
    float n1 = tanh_e(fmaf(r1, acc[SG][2][2 * (RI) + 1], XP[RI][2].y));       \
    float h0 = fmaf(z0, hprev[SG][RI][0] - n0, n0);                           \
    float h1 = fmaf(z1, hprev[SG][RI][1] - n1, n1);                           \
    hprev[SG][RI][0] = h0; hprev[SG][RI][1] = h1;                             \
    uint32_t hpk;                                                             \
    asm("cvt.rn.f16x2.f32 %0, %1, %2;" : "=r"(hpk) : "f"(h1), "f"(h0));       \
    *(uint32_t*)(smem + SH16(SG) + stoff[RI]) = hpk;                          \
} while (0)

__global__ __launch_bounds__(NTH, 1) void gru_mma_kernel(
    const float* __restrict__ bhh_f, const float* __restrict__ bhh_b) {
    extern __shared__ __align__(16) char smem[];
    const uint32_t sb = (uint32_t)__cvta_generic_to_shared(smem);

    const int dir  = blockIdx.y;
    const int b0r  = blockIdx.x * BM;
    const int tid  = threadIdx.x;
    const int w    = tid >> 5;
    const int lane = tid & 31;
    const int lr   = lane >> 2;
    const int lq   = lane & 3;

    const float* bhh = dir ? bhh_b : bhh_f;
    const float* xt  = g_xtab + dir * VV * GG;

    // ---- load w (swizzled) + zero h buffers ----
    {
        const uint4* gw0 = (const uint4*)(g_w0 + dir * (GG * HH));
        for (int idx = tid; idx < GG * 16; idx += NTH) {
            int n = idx >> 4, c = idx & 15;
            int off = n * 256 + ((c ^ (n & 7)) << 4);
            *(uint4*)(smem + SW0 + off) = gw0[idx];
        }
        for (int idx = tid; idx < 512; idx += NTH)
            ((uint4*)(smem + SH16(0)))[idx] = make_uint4(0, 0, 0, 0);
    }

    float bias_n[2];
    #pragma unroll
    for (int c = 0; c < 2; c++)
        bias_n[c] = bhh[2 * 128 + 8 * w + 2 * lq + c];

    // ldmatrix addressing: precomputed offsets (inner loop = IADD only)
    const int ar  = lane & 15;
    const int ahi = lane >> 4;
    const int asw = ar & 7;
    const int bj  = lane >> 3;
    const int bsw = lane & 7;
    const int brow = (24 * w + (lane & 7)) * 256;

    uint32_t aoff[4][2], boff[4];
    #pragma unroll
    for (int kc2 = 0; kc2 < 4; kc2++) {
        aoff[kc2][0] = (uint32_t)(((4 * kc2 + 0 + ahi) ^ asw) << 4);
        aoff[kc2][1] = (uint32_t)(((4 * kc2 + 2 + ahi) ^ asw) << 4);
        boff[kc2]    = (uint32_t)(((4 * kc2 + bj) ^ bsw) << 4);
    }
    const uint32_t abase0 = sb + SH16(0) + ar * 256;
    const uint32_t abase1 = sb + SH16(1) + ar * 256;
    const uint32_t bbase1 = sb + SW0 + brow + 1 * 2048;
    const uint32_t bbase2 = sb + SW0 + brow + 2 * 2048;

    int stoff[2];
    #pragma unroll
    for (int ri = 0; ri < 2; ri++)
        stoff[ri] = (lr + 8 * ri) * 256 + ((w ^ lr) << 4) + 4 * lq;

    __syncthreads();

    // cache B fragments for nt=0 only (register budget)
    uint32_t Brg0[4][4];
    #pragma unroll
    for (int kc2 = 0; kc2 < 4; kc2++)
        ldsm4(Brg0[kc2][0], Brg0[kc2][1], Brg0[kc2][2], Brg0[kc2][3],
              sb + SW0 + brow + boff[kc2]);

    float hprev[2][2][2];
    float acc[2][3][4];
    #pragma unroll
    for (int s = 0; s < 2; s++) {
        #pragma unroll
        for (int ri = 0; ri < 2; ri++)
            #pragma unroll
            for (int c = 0; c < 2; c++) hprev[s][ri][c] = 0.0f;
        #pragma unroll
        for (int rg = 0; rg < 4; rg++) {
            acc[s][0][rg] = 0.0f;
            acc[s][1][rg] = 0.0f;
            acc[s][2][rg] = bias_n[rg & 1];
        }
    }

    // xp0: stream-0 gather, prefetched one step ahead; xp1 at t-top.
    float2 xp0[2][3], xp1[2][3];
    {
        const int tcol = dir ? (TT - 1) : 0;
        const int* tokrow = g_tokT + tcol * BATCH + b0r;
        #pragma unroll
        for (int ri = 0; ri < 2; ri++) {
            int tok = tokrow[8 * ri + lr];
            const float2* xr = (const float2*)(xt + tok * GG + 24 * w);
            #pragma unroll
            for (int u = 0; u < 3; u++) xp0[ri][u] = xr[4 * u + lq];
        }
    }

    #pragma unroll 1
    for (int t = 0; t < TT; t++) {
        const int tcol = dir ? (TT - 1 - t) : t;

        // xp1 for stream 1 (consumed in phase 1, full phase of lead time)
        {
            const int* tokrow = g_tokT + tcol * BATCH + b0r + 16;
            #pragma unroll
            for (int ri = 0; ri < 2; ri++) {
                int tok = tokrow[8 * ri + lr];
                const float2* xr = (const float2*)(xt + tok * GG + 24 * w);
                #pragma unroll
                for (int u = 0; u < 3; u++) xp1[ri][u] = xr[4 * u + lq];
            }
        }

        // ---------------- phase 0: mma stream 1, gates stream 0 ----------
        {
            #pragma unroll
            for (int rg = 0; rg < 4; rg++) {
                acc[1][0][rg] = 0.0f; acc[1][1][rg] = 0.0f;
                acc[1][2][rg] = bias_n[rg & 1];
            }
            const bool do_mma = (t > 0);
            #pragma unroll
            for (int kc2 = 0; kc2 < 4; kc2++) {
                uint32_t a0[8];
                if (do_mma) {
                    ldsm4(a0[0], a0[1], a0[2], a0[3], abase1 + aoff[kc2][0]);
                    ldsm4(a0[4], a0[5], a0[6], a0[7], abase1 + aoff[kc2][1]);
                }
                if (kc2 == 1) GATE_PAIR(0, xp0, 0);
                if (kc2 == 3) GATE_PAIR(1, xp0, 0);
                if (do_mma) {
                    mma16816(acc[1][0], a0 + 0, Brg0[kc2][0], Brg0[kc2][1]);
                    mma16816(acc[1][0], a0 + 4, Brg0[kc2][2], Brg0[kc2][3]);
                    uint32_t b1[4], b2[4];
                    ldsm4(b1[0], b1[1], b1[2], b1[3], bbase1 + boff[kc2]);
                    mma16816(acc[1][1], a0 + 0, b1[0], b1[1]);
                    mma16816(acc[1][1], a0 + 4, b1[2], b1[3]);
                    ldsm4(b2[0], b2[1], b2[2], b2[3], bbase2 + boff[kc2]);
                    mma16816(acc[1][2], a0 + 0, b2[0], b2[1]);
                    mma16816(acc[1][2], a0 + 4, b2[2], b2[3]);
                }
            }
            __syncthreads();
        }

        // ---------------- phase 1: mma stream 0, gates stream 1 ----------
        {
            #pragma unroll
            for (int rg = 0; rg < 4; rg++) {
                acc[0][0][rg] = 0.0f; acc[0][1][rg] = 0.0f;
                acc[0][2][rg] = bias_n[rg & 1];
            }
            // prefetch xp0 for t+1 (consumed in next step's phase 0)
            {
                const int tn = (t + 1 < TT) ? t + 1 : t;
                const int tcoln = dir ? (TT - 1 - tn) : tn;
                const int* tokrow = g_tokT + tcoln * BATCH + b0r;
                #pragma unroll
                for (int ri = 0; ri < 2; ri++) {
                    int tok = tokrow[8 * ri + lr];
                    const float2* xr = (const float2*)(xt + tok * GG + 24 * w);
                    #pragma unroll
                    for (int u = 0; u < 3; u++) xp0[ri][u] = xr[4 * u + lq];
                }
            }
            const bool do_mma = (t < TT - 1);
            #pragma unroll
            for (int kc2 = 0; kc2 < 4; kc2++) {
                uint32_t a0[8];
                if (do_mma) {
                    ldsm4(a0[0], a0[1], a0[2], a0[3], abase0 + aoff[kc2][0]);
                    ldsm4(a0[4], a0[5], a0[6], a0[7], abase0 + aoff[kc2][1]);
                }
                if (kc2 == 1) GATE_PAIR(0, xp1, 1);
                if (kc2 == 3) GATE_PAIR(1, xp1, 1);
                if (do_mma) {
                    mma16816(acc[0][0], a0 + 0, Brg0[kc2][0], Brg0[kc2][1]);
                    mma16816(acc[0][0], a0 + 4, Brg0[kc2][2], Brg0[kc2][3]);
                    uint32_t b1[4], b2[4];
                    ldsm4(b1[0], b1[1], b1[2], b1[3], bbase1 + boff[kc2]);
                    mma16816(acc[0][1], a0 + 0, b1[0], b1[1]);
                    mma16816(acc[0][1], a0 + 4, b1[2], b1[3]);
                    ldsm4(b2[0], b2[1], b2[2], b2[3], bbase2 + boff[kc2]);
                    mma16816(acc[0][2], a0 + 0, b2[0], b2[1]);
                    mma16816(acc[0][2], a0 + 4, b2[2], b2[3]);
                }
            }
            __syncthreads();
        }
    }

    // final hidden -> feat
    #pragma unroll
    for (int s = 0; s < 2; s++)
        #pragma unroll
        for (int ri = 0; ri < 2; ri++)
            #pragma unroll
            for (int c = 0; c < 2; c++) {
                int m = 16 * s + lr + 8 * ri;
                int j = 8 * w + 2 * lq + c;
                g_feat[(b0r + m) * EE + dir * HH + j] = hprev[s][ri][c];
            }
}

// ---------------------------------------------------------------------------
// Head: one row per warp; down-proj via 8-lane groups; thread-per-column
// projection over the CTA's 8 rows. grid 256 x 256 threads.
// ---------------------------------------------------------------------------
#define HB 8
__global__ __launch_bounds__(256) void head_kernel(
    const int* __restrict__ lang_ids,
    const float* __restrict__ down_w, const float* __restrict__ down_b,
    const float* __restrict__ up_b,
    const float* __restrict__ ln_g,   const float* __restrict__ ln_b,
    const float* __restrict__ proj_w, const float* __restrict__ proj_b,
    float* __restrict__ out) {
    __shared__ float y_s[HB][EE];
    const int tid = threadIdx.x, w = tid >> 5, lane = tid & 31;
    const int b0 = blockIdx.x * HB;
    const int b = b0 + w;
    const int l = lang_ids[b];
    const float* fb = g_feat + b * EE;

    float4 f4[8];
    #pragma unroll
    for (int c = 0; c < 8; c++)
        f4[c] = *(const float4*)(fb + (lane & 7) * 4 + 32 * c);

    float hid = 0.0f;
    const float* dwb = down_w + l * BNK * EE;
    #pragma unroll
    for (int g = 0; g < 8; g++) {
        const int d = 4 * g + (lane >> 3);
        const float* wr = dwb + d * EE + (lane & 7) * 4;
        float s = 0.0f;
        #pragma unroll
        for (int c = 0; c < 8; c++) {
            float4 wv = *(const float4*)(wr + 32 * c);
            s = fmaf(f4[c].x, wv.x, s); s = fmaf(f4[c].y, wv.y, s);
            s = fmaf(f4[c].z, wv.z, s); s = fmaf(f4[c].w, wv.w, s);
        }
        s += __shfl_xor_sync(0xffffffffu, s, 1);
        s += __shfl_xor_sync(0xffffffffu, s, 2);
        s += __shfl_xor_sync(0xffffffffu, s, 4);
        float got = __shfl_sync(0xffffffffu, s, (lane & 3) * 8);
        if ((lane >> 2) == g) hid = got;
    }
    hid += down_b[l * BNK + lane];
    hid = 0.5f * hid * (1.0f + erff(hid * 0.7071067811865476f));

    const float4 fx0 = *(const float4*)(fb + lane * 8);
    const float4 fx1 = *(const float4*)(fb + lane * 8 + 4);
    float4 a0 = *(const float4*)(up_b + l * EE + lane * 8);
    float4 a1 = *(const float4*)(up_b + l * EE + lane * 8 + 4);
    const float* uwb = g_upwT + l * BNK * EE;
    #pragma unroll 4
    for (int d = 0; d < BNK; d++) {
        float hd = __shfl_sync(0xffffffffu, hid, d);
        float4 u0 = *(const float4*)(uwb + d * EE + lane * 8);
        float4 u1 = *(const float4*)(uwb + d * EE + lane * 8 + 4);
        a0.x = fmaf(hd, u0.x, a0.x); a0.y = fmaf(hd, u0.y, a0.y);
        a0.z = fmaf(hd, u0.z, a0.z); a0.w = fmaf(hd, u0.w, a0.w);
        a1.x = fmaf(hd, u1.x, a1.x); a1.y = fmaf(hd, u1.y, a1.y);
        a1.z = fmaf(hd, u1.z, a1.z); a1.w = fmaf(hd, u1.w, a1.w);
    }
    float x[8] = {fx0.x + a0.x, fx0.y + a0.y, fx0.z + a0.z, fx0.w + a0.w,
                  fx1.x + a1.x, fx1.y + a1.y, fx1.z + a1.z, fx1.w + a1.w};
    float s1 = 0.0f, s2 = 0.0f;
    #pragma unroll
    for (int j = 0; j < 8; j++) { s1 += x[j]; s2 = fmaf(x[j], x[j], s2); }
    #pragma unroll
    for (int o = 16; o; o >>= 1) {
        s1 += __shfl_xor_sync(0xffffffffu, s1, o);
        s2 += __shfl_xor_sync(0xffffffffu, s2, o);
    }
    const float mu = s1 * (1.0f / EE);
    const float rstd = rsqrtf(s2 * (1.0f / EE) - mu * mu + 1e-5f);
    const float4 g0 = *(const float4*)(ln_g + l * EE + lane * 8);
    const float4 g1 = *(const float4*)(ln_g + l * EE + lane * 8 + 4);
    const float4 bb0 = *(const float4*)(ln_b + l * EE + lane * 8);
    const float4 bb1 = *(const float4*)(ln_b + l * EE + lane * 8 + 4);
    float4 y0, y1;
    y0.x = (x[0]-mu)*rstd*g0.x + bb0.x;  y0.y = (x[1]-mu)*rstd*g0.y + bb0.y;
    y0.z = (x[2]-mu)*rstd*g0.z + bb0.z;  y0.w = (x[3]-mu)*rstd*g0.w + bb0.w;
    y1.x = (x[4]-mu)*rstd*g1.x + bb1.x;  y1.y = (x[5]-mu)*rstd*g1.y + bb1.y;
    y1.z = (x[6]-mu)*rstd*g1.z + bb1.z;  y1.w = (x[7]-mu)*rstd*g1.w + bb1.w;
    *(float4*)(&y_s[w][lane * 8])     = y0;
    *(float4*)(&y_s[w][lane * 8 + 4]) = y1;
    __syncthreads();

    float accv[HB];
    #pragma unroll
    for (int r = 0; r < HB; r++) accv[r] = proj_b[tid];
    const float* pw = proj_w + tid * EE;
    for (int e = 0; e < EE; e += 4) {
        float4 wv = *(const float4*)(pw + e);
        #pragma unroll
        for (int r = 0; r < HB; r++) {
            float4 yv = *(const float4*)(&y_s[r][e]);
            accv[r] = fmaf(wv.x, yv.x, accv[r]);
            accv[r] = fmaf(wv.y, yv.y, accv[r]);
            accv[r] = fmaf(wv.z, yv.z, accv[r]);
            accv[r] = fmaf(wv.w, yv.w, accv[r]);
        }
    }
    #pragma unroll
    for (int r = 0; r < HB; r++) out[(b0 + r) * OO + tid] = accv[r];
}

// ---------------------------------------------------------------------------
extern "C" void kernel_launch(void* const* d_in, const int* in_sizes, int n_in,
                              void* d_out, int out_size) {
    const int*   tokens = (const int*)d_in[0];
    const int*   lang   = (const int*)d_in[1];
    const float* ce     = (const float*)d_in[2];
    const float* wih_f  = (const float*)d_in[3];
    const float* whh_f  = (const float*)d_in[4];
    const float* bih_f  = (const float*)d_in[5];
    const float* bhh_f  = (const float*)d_in[6];
    const float* wih_b  = (const float*)d_in[7];
    const float* whh_b  = (const float*)d_in[8];
    const float* bih_b  = (const float*)d_in[9];
    const float* bhh_b  = (const float*)d_in[10];
    const float* down_w = (const float*)d_in[11];
    const float* down_b = (const float*)d_in[12];
    const float* up_w   = (const float*)d_in[13];
    const float* up_b   = (const float*)d_in[14];
    const float* ln_g   = (const float*)d_in[15];
    const float* ln_b   = (const float*)d_in[16];
    const float* proj_w = (const float*)d_in[17];
    const float* proj_b = (const float*)d_in[18];
    float* out = (float*)d_out;

    cudaFuncSetAttribute(gru_mma_kernel,
                         cudaFuncAttributeMaxDynamicSharedMemorySize, SMEM_TOTAL);
    const size_t xsmem = (size_t)(GG * CC + GG + 32 * CC) * sizeof(float);
    cudaFuncSetAttribute(xtab_kernel,
                         cudaFuncAttributeMaxDynamicSharedMemorySize, (int)xsmem);

    const int prep_elems = 2 * GG * HH + NLN * EE * BNK + BATCH * TT;
    prep_misc<<<(prep_elems + 255) / 256, 256>>>(whh_f, whh_b, up_w, tokens);
    xtab_kernel<<<dim3(8, 2), GG, xsmem>>>(ce, wih_f, bih_f, wih_b, bih_b,
                                           bhh_f, bhh_b);
    gru_mma_kernel<<<dim3(BATCH / BM, 2), NTH, SMEM_TOTAL>>>(bhh_f, bhh_b);
    head_kernel<<<BATCH / HB, 256>>>(lang, down_w, down_b, up_b,
                                     ln_g, ln_b, proj_w, proj_b, out);
}